// round 14
// baseline (speedup 1.0000x reference)
#include <cuda_runtime.h>
#include <cuda_bf16.h>
#include <cstdint>
#include <math.h>

#define B_  64
#define T_  1024
#define I_  512
#define H_  1024

// ===================== warp-mma helpers =====================================
__device__ __forceinline__ uint32_t smem_u32(const void* p) {
    uint32_t a;
    asm("{ .reg .u64 t; cvta.to.shared.u64 t, %1; cvt.u32.u64 %0, t; }"
        : "=r"(a) : "l"(p));
    return a;
}
__device__ __forceinline__ void ldsm4(uint32_t& r0, uint32_t& r1,
                                      uint32_t& r2, uint32_t& r3, uint32_t a) {
    asm volatile("ldmatrix.sync.aligned.m8n8.x4.shared.b16 {%0,%1,%2,%3}, [%4];"
                 : "=r"(r0), "=r"(r1), "=r"(r2), "=r"(r3) : "r"(a));
}
__device__ __forceinline__ void mma_bf16(float* c, const uint32_t* a,
                                         uint32_t b0, uint32_t b1) {
    asm volatile("mma.sync.aligned.m16n8k16.row.col.f32.bf16.bf16.f32 "
                 "{%0,%1,%2,%3}, {%4,%5,%6,%7}, {%8,%9}, {%0,%1,%2,%3};"
                 : "+f"(c[0]), "+f"(c[1]), "+f"(c[2]), "+f"(c[3])
                 : "r"(a[0]), "r"(a[1]), "r"(a[2]), "r"(a[3]),
                   "r"(b0), "r"(b1));
}
__device__ __forceinline__ void poll_ge(unsigned* p, unsigned tgt) {
    unsigned v;
    do { asm volatile("ld.acquire.gpu.global.u32 %0, [%1];"
                      : "=r"(v) : "l"(p)); } while (v < tgt);
}
__device__ __forceinline__ void rel_add1(unsigned* p) {
    asm volatile("red.release.gpu.global.add.u32 [%0], 1;" :: "l"(p) : "memory");
}
__device__ __forceinline__ void st_rel(unsigned* p, unsigned v) {
    asm volatile("st.release.gpu.global.u32 [%0], %1;" :: "l"(p), "r"(v)
                 : "memory");
}
// split fp32 pair -> packed bf16x2 hi + lo
__device__ __forceinline__ void split2(float a, float b,
                                       uint32_t& h, uint32_t& l) {
    __nv_bfloat16 ha = __float2bfloat16_rn(a);
    __nv_bfloat16 hb = __float2bfloat16_rn(b);
    __nv_bfloat16 la = __float2bfloat16_rn(a - __bfloat162float(ha));
    __nv_bfloat16 lb = __float2bfloat16_rn(b - __bfloat162float(hb));
    __nv_bfloat162 hp; hp.x = ha; hp.y = hb;
    __nv_bfloat162 lp; lp.x = la; lp.y = lb;
    h = *(uint32_t*)&hp; l = *(uint32_t*)&lp;
}
// swizzled offset in a [.][64 k] bf16 tile (128 B rows, 8x16B chunks)
__device__ __forceinline__ uint32_t tswz64c(int row, int chunk) {
    return (uint32_t)(row * 128) + (uint32_t)((chunk ^ (row & 7)) << 4);
}
// swizzled offset in a [.][128 k] bf16 tile (256 B rows)
__device__ __forceinline__ uint32_t tswz(int row, int k) {
    uint32_t kb = (uint32_t)(k * 2);
    return (uint32_t)(row * 256) + ((((kb >> 4) ^ (row & 7)) << 4) | (kb & 15));
}

// ===================== global scratch =======================================
__device__ unsigned char g_hsp[2][2][8][16384];      // h bf16 hi/lo tile images
__device__ float    g_part[2][8][B_ * H_];           // K-group partials
__device__ unsigned g_prodf[16][8];                  // h published: [ng][kg]
__device__ unsigned g_done[16][8];                   // partials in:  [ng][kg]
__device__ unsigned g_rdone[8];                      // h-image read counters
__device__ __nv_bfloat16 g_iwt[2][H_ * I_];          // input_w^T hi/lo [n][k]

__global__ void init_kernel() {
    int idx = blockIdx.x * blockDim.x + threadIdx.x;   // 16384 threads
    ((uint4*)g_hsp[0])[idx] = make_uint4(0, 0, 0, 0);  // zero buf 0 (h0 = 0)
    if (idx < 128) { ((unsigned*)g_prodf)[idx] = 0u; ((unsigned*)g_done)[idx] = 0u; }
    if (idx < 8)  g_rdone[idx] = 0u;
}

// ===================== Phase 0: transpose + split input_w ===================
// g_iwt[h][n][k] = split_h(iw[k][n]); warp handles 32k x 32n block.
__global__ void __launch_bounds__(256)
convert_iw(const float* __restrict__ iw) {
    const int tid  = threadIdx.x;
    const int lane = tid & 31;
    const int gw   = blockIdx.x * 8 + (tid >> 5);   // 0..511
    const int n0   = (gw & 31) * 32;
    const int k0   = (gw >> 5) * 32;
    const int n    = n0 + lane;

    float w[32];
#pragma unroll
    for (int kr = 0; kr < 32; ++kr)
        w[kr] = iw[(size_t)(k0 + kr) * H_ + n];

    uint32_t hu[16], lu[16];
#pragma unroll
    for (int j = 0; j < 16; ++j)
        split2(w[2 * j], w[2 * j + 1], hu[j], lu[j]);

    char* dh = (char*)g_iwt[0] + (size_t)n * 1024 + k0 * 2;
    char* dl = (char*)g_iwt[1] + (size_t)n * 1024 + k0 * 2;
#pragma unroll
    for (int j = 0; j < 4; ++j) {
        *(uint4*)(dh + j * 16) = *(uint4*)&hu[j * 4];
        *(uint4*)(dl + j * 16) = *(uint4*)&lu[j * 4];
    }
}

// ===================== Phase 1: xp = x @ input_w + b (HMMA) =================
// CTA tile M=64 x N=128 x K=512 (k-tiles of 64); 8 warps = 2(M) x 4(N),
// warp tile 32x32; split-bf16 3-product.
#define PJ_A_HI 0
#define PJ_A_LO 8192
#define PJ_W_HI 16384
#define PJ_W_LO 32768

__global__ void __launch_bounds__(256, 2)
proj_mma(const float* __restrict__ x, const float* __restrict__ bias,
         float* __restrict__ out) {
    __shared__ char smem[49152];
    const uint32_t sb = smem_u32(smem);
    const int tid  = threadIdx.x;
    const int wid  = tid >> 5;
    const int lane = tid & 31;
    const int n0g  = blockIdx.x * 128;
    const int m0g  = blockIdx.y * 64;

    const int m0w = (wid & 1) * 32;
    const int n0w = (wid >> 1) * 32;
    const int lr  = lane & 15;
    const int kh  = lane >> 4;

    const uint32_t a_hi0 = sb + PJ_A_HI + (uint32_t)((m0w + lr) * 128);
    const uint32_t a_hi1 = a_hi0 + 16 * 128;
    const uint32_t a_lo0 = sb + PJ_A_LO + (uint32_t)((m0w + lr) * 128);
    const uint32_t a_lo1 = a_lo0 + 16 * 128;
    const uint32_t w_hi0 = sb + PJ_W_HI + (uint32_t)((n0w + lr) * 128);
    const uint32_t w_hi1 = w_hi0 + 16 * 128;
    const uint32_t w_lo0 = sb + PJ_W_LO + (uint32_t)((n0w + lr) * 128);
    const uint32_t w_lo1 = w_lo0 + 16 * 128;

    float c[2][4][4];
#pragma unroll
    for (int i = 0; i < 2; ++i)
#pragma unroll
        for (int j = 0; j < 4; ++j)
            c[i][j][0] = c[i][j][1] = c[i][j][2] = c[i][j][3] = 0.f;

    // staging roles
    const int arow = tid >> 2, akq = tid & 3;        // A: 64 rows x 4 quarters
    const int wrow = tid >> 1, whalf = tid & 1;      // W: 128 rows x 2 halves

    for (int kt = 0; kt < 8; ++kt) {
        // ---- stage A (x fp32 -> bf16 hi/lo, swizzled) ----
        {
            const float* src = x + (size_t)(m0g + arow) * I_ + kt * 64 + akq * 16;
            float4 f0 = *(const float4*)(src + 0);
            float4 f1 = *(const float4*)(src + 4);
            float4 f2 = *(const float4*)(src + 8);
            float4 f3 = *(const float4*)(src + 12);
            uint32_t hu[8], lu[8];
            split2(f0.x, f0.y, hu[0], lu[0]); split2(f0.z, f0.w, hu[1], lu[1]);
            split2(f1.x, f1.y, hu[2], lu[2]); split2(f1.z, f1.w, hu[3], lu[3]);
            split2(f2.x, f2.y, hu[4], lu[4]); split2(f2.z, f2.w, hu[5], lu[5]);
            split2(f3.x, f3.y, hu[6], lu[6]); split2(f3.z, f3.w, hu[7], lu[7]);
#pragma unroll
            for (int c8 = 0; c8 < 2; ++c8) {
                uint32_t off = tswz64c(arow, akq * 2 + c8);
                *(uint4*)(smem + PJ_A_HI + off) = *(uint4*)&hu[c8 * 4];
                *(uint4*)(smem + PJ_A_LO + off) = *(uint4*)&lu[c8 * 4];
            }
        }
        // ---- stage W (pre-split bf16, raw copy + swizzle) ----
        {
            const char* sh = (const char*)g_iwt[0]
                           + (size_t)(n0g + wrow) * 1024 + kt * 128 + whalf * 64;
            const char* sl = (const char*)g_iwt[1]
                           + (size_t)(n0g + wrow) * 1024 + kt * 128 + whalf * 64;
#pragma unroll
            for (int j = 0; j < 4; ++j) {
                uint4 vh = __ldcg((const uint4*)(sh + j * 16));
                uint4 vl = __ldcg((const uint4*)(sl + j * 16));
                uint32_t off = tswz64c(wrow, whalf * 4 + j);
                *(uint4*)(smem + PJ_W_HI + off) = vh;
                *(uint4*)(smem + PJ_W_LO + off) = vl;
            }
        }
        __syncthreads();

        // ---- mma: 4 k16-steps, 3 split products ----
#pragma unroll
        for (int s = 0; s < 4; ++s) {
            const uint32_t co = (uint32_t)(((2 * s + kh) ^ (lr & 7)) << 4);
            uint32_t ah[2][4], al[2][4], bh[4][2], bl[4][2];
            uint32_t x0, x1, x2, x3;
            ldsm4(ah[0][0], ah[0][1], ah[0][2], ah[0][3], a_hi0 + co);
            ldsm4(ah[1][0], ah[1][1], ah[1][2], ah[1][3], a_hi1 + co);
            ldsm4(al[0][0], al[0][1], al[0][2], al[0][3], a_lo0 + co);
            ldsm4(al[1][0], al[1][1], al[1][2], al[1][3], a_lo1 + co);
            ldsm4(x0, x1, x2, x3, w_hi0 + co);
            bh[0][0] = x0; bh[0][1] = x2; bh[1][0] = x1; bh[1][1] = x3;
            ldsm4(x0, x1, x2, x3, w_hi1 + co);
            bh[2][0] = x0; bh[2][1] = x2; bh[3][0] = x1; bh[3][1] = x3;
            ldsm4(x0, x1, x2, x3, w_lo0 + co);
            bl[0][0] = x0; bl[0][1] = x2; bl[1][0] = x1; bl[1][1] = x3;
            ldsm4(x0, x1, x2, x3, w_lo1 + co);
            bl[2][0] = x0; bl[2][1] = x2; bl[3][0] = x1; bl[3][1] = x3;
#pragma unroll
            for (int i = 0; i < 2; ++i)
#pragma unroll
                for (int j = 0; j < 4; ++j) {
                    mma_bf16(c[i][j], ah[i], bh[j][0], bh[j][1]);
                    mma_bf16(c[i][j], ah[i], bl[j][0], bl[j][1]);
                    mma_bf16(c[i][j], al[i], bh[j][0], bh[j][1]);
                }
        }
        __syncthreads();
    }

    // ---- epilogue: + bias, store fp32 ----
#pragma unroll
    for (int j = 0; j < 4; ++j) {
        const int col = n0g + n0w + j * 8 + 2 * (lane & 3);
        float2 bb = *(const float2*)(bias + col);
#pragma unroll
        for (int i = 0; i < 2; ++i) {
            const int r0 = m0g + m0w + i * 16 + (lane >> 2);
            *(float2*)(out + (size_t)r0 * H_ + col)
                = make_float2(c[i][j][0] + bb.x, c[i][j][1] + bb.y);
            *(float2*)(out + (size_t)(r0 + 8) * H_ + col)
                = make_float2(c[i][j][2] + bb.x, c[i][j][3] + bb.y);
        }
    }
}

// ===================== Phase 2: HMMA recurrence, flag-sync ==================
// 128 CTAs = 8 k-groups x 16 n-groups. CTA: M=64 x N=64 x K=128 split-bf16.
// Sync via single-writer flag words polled in parallel; 2-pass mma pipeline.
#define A_HI 0
#define A_LO 16384
#define W_HI 32768
#define W_LO 49152
#define RNN_SMEM_BYTES 65536

__global__ void __launch_bounds__(256, 1)
rnn_mma_kernel(const float* __restrict__ W, float* __restrict__ out) {
    extern __shared__ char smem[];
    const uint32_t sb = smem_u32(smem);
    const int tid  = threadIdx.x;
    const int wid  = tid >> 5;
    const int lane = tid & 31;
    const int kg   = blockIdx.x >> 4;    // 0..7
    const int ng   = blockIdx.x & 15;    // 0..15
    const int ksl  = kg * 128;
    const int nsl  = ng * 64;

    // ---- build W^T hi/lo tiles once ----
    for (int q = tid; q < 64 * 128; q += 256) {
        int k = q >> 6;
        int n = q & 63;
        float w = W[(size_t)(ksl + k) * H_ + nsl + n];
        __nv_bfloat16 hi = __float2bfloat16_rn(w);
        __nv_bfloat16 lo = __float2bfloat16_rn(w - __bfloat162float(hi));
        uint32_t off = tswz(n, k);
        *(unsigned short*)(smem + W_HI + off) = *(unsigned short*)&hi;
        *(unsigned short*)(smem + W_LO + off) = *(unsigned short*)&lo;
    }
    __syncthreads();

    const int m0  = (wid & 3) * 16;
    const int n0w = (wid >> 2) * 32;
    const int lr  = lane & 15;
    const int kh  = lane >> 4;

    const uint32_t a_row_hi = sb + A_HI + (uint32_t)((m0 + lr) * 256);
    const uint32_t a_row_lo = sb + A_LO + (uint32_t)((m0 + lr) * 256);
    const uint32_t w_row0_h = sb + W_HI + (uint32_t)((n0w + lr) * 256);
    const uint32_t w_row1_h = sb + W_HI + (uint32_t)((n0w + 16 + lr) * 256);
    const uint32_t w_row0_l = sb + W_LO + (uint32_t)((n0w + lr) * 256);
    const uint32_t w_row1_l = sb + W_LO + (uint32_t)((n0w + 16 + lr) * 256);
    const uint32_t swz_a = (uint32_t)(lane & 7);

    const int ra_ = m0 + (lane >> 2);
    const int rb_ = ra_ + 8;
    const int colb = n0w + 2 * (lane & 3);

    const int e    = tid * 2;
    const int rr   = e >> 6;
    const int cc   = e & 63;
    const int eb   = kg * 8 + rr;
    const int kg2  = ng >> 1;
    const int kimg = (ng & 1) * 64 + cc;
    const uint32_t hoff = tswz(eb, kimg);

    for (int t = 0; t < T_; ++t) {
        // ---- top waits: parallel flag polls ----
        if (tid < 16) {
            poll_ge(&g_prodf[2 * kg + (tid >> 3)][tid & 7], (unsigned)t);
        } else if (tid >= 32 && tid < 40) {
            if (t >= 2) poll_ge(&g_prodf[ng][tid - 32], (unsigned)(t - 1));
        } else if (tid == 64) {
            if (t >= 1) poll_ge(&g_rdone[kg2], 16u * (unsigned)t);
        }
        __syncthreads();

        // ---- prefetch xp ----
        size_t obase = ((size_t)eb * T_ + t) * H_ + nsl + cc;
        float2 xv = __ldcg((const float2*)(out + obase));

        // ---- stage A hi image ----
        const uint4* srcH = (const uint4*)(g_hsp[t & 1][0][kg]);
        const uint4* srcL = (const uint4*)(g_hsp[t & 1][1][kg]);
#pragma unroll
        for (int i = 0; i < 4; ++i) {
            uint4 vh = __ldcg(srcH + i * 256 + tid);
            *(uint4*)(smem + A_HI + i * 4096 + tid * 16) = vh;
        }
        __syncthreads();
        // ---- fire A lo stage; its latency hides under pass-1 mma ----
#pragma unroll
        for (int i = 0; i < 4; ++i) {
            uint4 vl = __ldcg(srcL + i * 256 + tid);
            *(uint4*)(smem + A_LO + i * 4096 + tid * 16) = vl;
        }

        float c[4][4];
#pragma unroll
        for (int j = 0; j < 4; ++j)
            c[j][0] = c[j][1] = c[j][2] = c[j][3] = 0.f;

        // ---- pass 1: Ahi*Whi + Ahi*Wlo ----
#pragma unroll
        for (int s = 0; s < 8; ++s) {
            const uint32_t ca  = (uint32_t)(((2 * s + kh) ^ swz_a) << 4);
            const uint32_t cw0 = (uint32_t)(((2 * s + kh) ^ (lr & 7)) << 4);
            uint32_t ah[4];
            uint32_t x0, x1, x2, x3;
            ldsm4(ah[0], ah[1], ah[2], ah[3], a_row_hi + ca);
            ldsm4(x0, x1, x2, x3, w_row0_h + cw0);
            uint32_t bh0 = x0, bh1 = x2, bh0b = x1, bh1b = x3;
            ldsm4(x0, x1, x2, x3, w_row1_h + cw0);
            uint32_t bh2 = x0, bh3 = x2, bh2b = x1, bh3b = x3;
            ldsm4(x0, x1, x2, x3, w_row0_l + cw0);
            uint32_t bl0 = x0, bl1 = x2, bl0b = x1, bl1b = x3;
            ldsm4(x0, x1, x2, x3, w_row1_l + cw0);
            uint32_t bl2 = x0, bl3 = x2, bl2b = x1, bl3b = x3;
            mma_bf16(c[0], ah, bh0, bh1);
            mma_bf16(c[1], ah, bh0b, bh1b);
            mma_bf16(c[2], ah, bh2, bh3);
            mma_bf16(c[3], ah, bh2b, bh3b);
            mma_bf16(c[0], ah, bl0, bl1);
            mma_bf16(c[1], ah, bl0b, bl1b);
            mma_bf16(c[2], ah, bl2, bl3);
            mma_bf16(c[3], ah, bl2b, bl3b);
        }
        __syncthreads();               // A_lo staged
        if (tid == 0) rel_add1(&g_rdone[kg]);

        // ---- pass 2: Alo*Whi ----
#pragma unroll
        for (int s = 0; s < 8; ++s) {
            const uint32_t ca  = (uint32_t)(((2 * s + kh) ^ swz_a) << 4);
            const uint32_t cw0 = (uint32_t)(((2 * s + kh) ^ (lr & 7)) << 4);
            uint32_t al[4];
            uint32_t x0, x1, x2, x3;
            ldsm4(al[0], al[1], al[2], al[3], a_row_lo + ca);
            ldsm4(x0, x1, x2, x3, w_row0_h + cw0);
            uint32_t bh0 = x0, bh1 = x2, bh0b = x1, bh1b = x3;
            ldsm4(x0, x1, x2, x3, w_row1_h + cw0);
            uint32_t bh2 = x0, bh3 = x2, bh2b = x1, bh3b = x3;
            mma_bf16(c[0], al, bh0, bh1);
            mma_bf16(c[1], al, bh0b, bh1b);
            mma_bf16(c[2], al, bh2, bh3);
            mma_bf16(c[3], al, bh2b, bh3b);
        }

        // ---- store partials (WAR cleared by top wait) ----
        {
            const int pr = t & 1;
            float* pa = &g_part[pr][kg][(size_t)ra_ * H_ + nsl + colb];
            float* pb = &g_part[pr][kg][(size_t)rb_ * H_ + nsl + colb];
#pragma unroll
            for (int j = 0; j < 4; ++j) {
                __stcg((float2*)(pa + j * 8), make_float2(c[j][0], c[j][1]));
                __stcg((float2*)(pb + j * 8), make_float2(c[j][2], c[j][3]));
            }
        }
        __syncthreads();
        if (tid == 0) st_rel(&g_done[ng][kg], (unsigned)(t + 1));
        if (tid < 8) poll_ge(&g_done[ng][tid], (unsigned)(t + 1));
        __syncthreads();

        // ---- reduce 8 partials, add xp, tanh, write out + split-h image ----
        {
            const int pr = t & 1;
            float2 s2 = make_float2(0.f, 0.f);
#pragma unroll
            for (int k2 = 0; k2 < 8; ++k2) {
                float2 pv = __ldcg((const float2*)(&g_part[pr][k2][(size_t)eb * H_ + nsl + cc]));
                s2.x += pv.x; s2.y += pv.y;
            }
            float2 hn;
            hn.x = tanhf(s2.x + xv.x);
            hn.y = tanhf(s2.y + xv.y);
            __stcg((float2*)(out + obase), hn);

            uint32_t hp, lp;
            split2(hn.x, hn.y, hp, lp);
            const int nb = (t + 1) & 1;
            __stcg((unsigned int*)(g_hsp[nb][0][kg2] + hoff), hp);
            __stcg((unsigned int*)(g_hsp[nb][1][kg2] + hoff), lp);
        }
        __syncthreads();
        if (tid == 0) st_rel(&g_prodf[ng][kg], (unsigned)(t + 1));
    }
}

// ===================== launch ===============================================
extern "C" void kernel_launch(void* const* d_in, const int* in_sizes, int n_in,
                              void* d_out, int out_size) {
    const float *x = nullptr, *hw = nullptr, *iw = nullptr, *bias = nullptr;
    for (int i = 0; i < n_in; ++i) {
        long long s = in_sizes[i];
        if      (s == (long long)B_ * T_ * I_) x    = (const float*)d_in[i];
        else if (s == (long long)H_ * H_)      hw   = (const float*)d_in[i];
        else if (s == (long long)I_ * H_)      iw   = (const float*)d_in[i];
        else if (s == (long long)H_)           bias = (const float*)d_in[i];
    }
    float* out = (float*)d_out;

    cudaFuncSetAttribute(rnn_mma_kernel,
                         cudaFuncAttributeMaxDynamicSharedMemorySize,
                         RNN_SMEM_BYTES);

    convert_iw<<<64, 256>>>(iw);
    proj_mma<<<dim3(8, 1024), 256>>>(x, bias, out);
    init_kernel<<<64, 256>>>();
    rnn_mma_kernel<<<128, 256, RNN_SMEM_BYTES>>>(hw, out);
}

// round 15
// speedup vs baseline: 1.6937x; 1.6937x over previous
#include <cuda_runtime.h>
#include <cuda_bf16.h>
#include <cstdint>
#include <math.h>

#define B_  64
#define T_  1024
#define I_  512
#define H_  1024

// ===================== warp-mma helpers =====================================
__device__ __forceinline__ uint32_t smem_u32(const void* p) {
    uint32_t a;
    asm("{ .reg .u64 t; cvta.to.shared.u64 t, %1; cvt.u32.u64 %0, t; }"
        : "=r"(a) : "l"(p));
    return a;
}
__device__ __forceinline__ void ldsm4(uint32_t& r0, uint32_t& r1,
                                      uint32_t& r2, uint32_t& r3, uint32_t a) {
    asm volatile("ldmatrix.sync.aligned.m8n8.x4.shared.b16 {%0,%1,%2,%3}, [%4];"
                 : "=r"(r0), "=r"(r1), "=r"(r2), "=r"(r3) : "r"(a));
}
__device__ __forceinline__ void mma_bf16(float* c, const uint32_t* a,
                                         uint32_t b0, uint32_t b1) {
    asm volatile("mma.sync.aligned.m16n8k16.row.col.f32.bf16.bf16.f32 "
                 "{%0,%1,%2,%3}, {%4,%5,%6,%7}, {%8,%9}, {%0,%1,%2,%3};"
                 : "+f"(c[0]), "+f"(c[1]), "+f"(c[2]), "+f"(c[3])
                 : "r"(a[0]), "r"(a[1]), "r"(a[2]), "r"(a[3]),
                   "r"(b0), "r"(b1));
}
__device__ __forceinline__ void poll_ge(unsigned* p, unsigned tgt) {
    unsigned v;
    do { asm volatile("ld.acquire.gpu.global.u32 %0, [%1];"
                      : "=r"(v) : "l"(p)); } while (v < tgt);
}
__device__ __forceinline__ void rel_add1(unsigned* p) {
    asm volatile("red.release.gpu.global.add.u32 [%0], 1;" :: "l"(p) : "memory");
}
// split fp32 pair -> packed bf16x2 hi + lo
__device__ __forceinline__ void split2(float a, float b,
                                       uint32_t& h, uint32_t& l) {
    __nv_bfloat16 ha = __float2bfloat16_rn(a);
    __nv_bfloat16 hb = __float2bfloat16_rn(b);
    __nv_bfloat16 la = __float2bfloat16_rn(a - __bfloat162float(ha));
    __nv_bfloat16 lb = __float2bfloat16_rn(b - __bfloat162float(hb));
    __nv_bfloat162 hp; hp.x = ha; hp.y = hb;
    __nv_bfloat162 lp; lp.x = la; lp.y = lb;
    h = *(uint32_t*)&hp; l = *(uint32_t*)&lp;
}
// swizzled offset in a [.][64 k] bf16 tile (128 B rows, 8x16B chunks)
__device__ __forceinline__ uint32_t tswz64c(int row, int chunk) {
    return (uint32_t)(row * 128) + (uint32_t)((chunk ^ (row & 7)) << 4);
}
// swizzled offset in a [.][128 k] bf16 tile (256 B rows)
__device__ __forceinline__ uint32_t tswz(int row, int k) {
    uint32_t kb = (uint32_t)(k * 2);
    return (uint32_t)(row * 256) + ((((kb >> 4) ^ (row & 7)) << 4) | (kb & 15));
}

// ===================== global scratch =======================================
__device__ unsigned char g_hsp[2][2][8][16384];      // h bf16 hi/lo tile images
__device__ float    g_part[2][8][B_ * H_];           // K-group partials
__device__ unsigned g_prod[16];                      // per-ng h-produced counters
__device__ unsigned g_rdone[8];                      // per-kg h-staged counters
__device__ unsigned g_bar2[16];                      // per-ng partial-ready counters
__device__ __nv_bfloat16 g_iwt[2][H_ * I_];          // input_w^T hi/lo [n][k]

__global__ void init_kernel() {
    int idx = blockIdx.x * blockDim.x + threadIdx.x;   // 16384 threads
    ((uint4*)g_hsp[0])[idx] = make_uint4(0, 0, 0, 0);  // zero buf 0 (h0 = 0)
    if (idx < 16) { g_prod[idx] = 0u; g_bar2[idx] = 0u; }
    if (idx < 8)  g_rdone[idx] = 0u;
}

// ===================== Phase 0: transpose + split input_w ===================
// g_iwt[h][n][k] = split_h(iw[k][n]); warp handles 32k x 32n block.
__global__ void __launch_bounds__(256)
convert_iw(const float* __restrict__ iw) {
    const int tid  = threadIdx.x;
    const int lane = tid & 31;
    const int gw   = blockIdx.x * 8 + (tid >> 5);   // 0..511
    const int n0   = (gw & 31) * 32;
    const int k0   = (gw >> 5) * 32;
    const int n    = n0 + lane;

    float w[32];
#pragma unroll
    for (int kr = 0; kr < 32; ++kr)
        w[kr] = iw[(size_t)(k0 + kr) * H_ + n];

    uint32_t hu[16], lu[16];
#pragma unroll
    for (int j = 0; j < 16; ++j)
        split2(w[2 * j], w[2 * j + 1], hu[j], lu[j]);

    char* dh = (char*)g_iwt[0] + (size_t)n * 1024 + k0 * 2;
    char* dl = (char*)g_iwt[1] + (size_t)n * 1024 + k0 * 2;
#pragma unroll
    for (int j = 0; j < 4; ++j) {
        *(uint4*)(dh + j * 16) = *(uint4*)&hu[j * 4];
        *(uint4*)(dl + j * 16) = *(uint4*)&lu[j * 4];
    }
}

// ===================== Phase 1: xp = x @ input_w + b (HMMA) =================
// CTA tile M=64 x N=128 x K=512 (k-tiles of 64); 8 warps = 2(M) x 4(N),
// warp tile 32x32; split-bf16 3-product.  (round-14 version: measured ~0.5ms)
#define PJ_A_HI 0
#define PJ_A_LO 8192
#define PJ_W_HI 16384
#define PJ_W_LO 32768

__global__ void __launch_bounds__(256, 2)
proj_mma(const float* __restrict__ x, const float* __restrict__ bias,
         float* __restrict__ out) {
    __shared__ char smem[49152];
    const uint32_t sb = smem_u32(smem);
    const int tid  = threadIdx.x;
    const int wid  = tid >> 5;
    const int lane = tid & 31;
    const int n0g  = blockIdx.x * 128;
    const int m0g  = blockIdx.y * 64;

    const int m0w = (wid & 1) * 32;
    const int n0w = (wid >> 1) * 32;
    const int lr  = lane & 15;
    const int kh  = lane >> 4;

    const uint32_t a_hi0 = sb + PJ_A_HI + (uint32_t)((m0w + lr) * 128);
    const uint32_t a_hi1 = a_hi0 + 16 * 128;
    const uint32_t a_lo0 = sb + PJ_A_LO + (uint32_t)((m0w + lr) * 128);
    const uint32_t a_lo1 = a_lo0 + 16 * 128;
    const uint32_t w_hi0 = sb + PJ_W_HI + (uint32_t)((n0w + lr) * 128);
    const uint32_t w_hi1 = w_hi0 + 16 * 128;
    const uint32_t w_lo0 = sb + PJ_W_LO + (uint32_t)((n0w + lr) * 128);
    const uint32_t w_lo1 = w_lo0 + 16 * 128;

    float c[2][4][4];
#pragma unroll
    for (int i = 0; i < 2; ++i)
#pragma unroll
        for (int j = 0; j < 4; ++j)
            c[i][j][0] = c[i][j][1] = c[i][j][2] = c[i][j][3] = 0.f;

    const int arow = tid >> 2, akq = tid & 3;        // A: 64 rows x 4 quarters
    const int wrow = tid >> 1, whalf = tid & 1;      // W: 128 rows x 2 halves

    for (int kt = 0; kt < 8; ++kt) {
        // ---- stage A (x fp32 -> bf16 hi/lo, swizzled) ----
        {
            const float* src = x + (size_t)(m0g + arow) * I_ + kt * 64 + akq * 16;
            float4 f0 = *(const float4*)(src + 0);
            float4 f1 = *(const float4*)(src + 4);
            float4 f2 = *(const float4*)(src + 8);
            float4 f3 = *(const float4*)(src + 12);
            uint32_t hu[8], lu[8];
            split2(f0.x, f0.y, hu[0], lu[0]); split2(f0.z, f0.w, hu[1], lu[1]);
            split2(f1.x, f1.y, hu[2], lu[2]); split2(f1.z, f1.w, hu[3], lu[3]);
            split2(f2.x, f2.y, hu[4], lu[4]); split2(f2.z, f2.w, hu[5], lu[5]);
            split2(f3.x, f3.y, hu[6], lu[6]); split2(f3.z, f3.w, hu[7], lu[7]);
#pragma unroll
            for (int c8 = 0; c8 < 2; ++c8) {
                uint32_t off = tswz64c(arow, akq * 2 + c8);
                *(uint4*)(smem + PJ_A_HI + off) = *(uint4*)&hu[c8 * 4];
                *(uint4*)(smem + PJ_A_LO + off) = *(uint4*)&lu[c8 * 4];
            }
        }
        // ---- stage W (pre-split bf16, raw copy + swizzle) ----
        {
            const char* sh = (const char*)g_iwt[0]
                           + (size_t)(n0g + wrow) * 1024 + kt * 128 + whalf * 64;
            const char* sl = (const char*)g_iwt[1]
                           + (size_t)(n0g + wrow) * 1024 + kt * 128 + whalf * 64;
#pragma unroll
            for (int j = 0; j < 4; ++j) {
                uint4 vh = __ldcg((const uint4*)(sh + j * 16));
                uint4 vl = __ldcg((const uint4*)(sl + j * 16));
                uint32_t off = tswz64c(wrow, whalf * 4 + j);
                *(uint4*)(smem + PJ_W_HI + off) = vh;
                *(uint4*)(smem + PJ_W_LO + off) = vl;
            }
        }
        __syncthreads();

        // ---- mma: 4 k16-steps, 3 split products ----
#pragma unroll
        for (int s = 0; s < 4; ++s) {
            const uint32_t co = (uint32_t)(((2 * s + kh) ^ (lr & 7)) << 4);
            uint32_t ah[2][4], al[2][4], bh[4][2], bl[4][2];
            uint32_t x0, x1, x2, x3;
            ldsm4(ah[0][0], ah[0][1], ah[0][2], ah[0][3], a_hi0 + co);
            ldsm4(ah[1][0], ah[1][1], ah[1][2], ah[1][3], a_hi1 + co);
            ldsm4(al[0][0], al[0][1], al[0][2], al[0][3], a_lo0 + co);
            ldsm4(al[1][0], al[1][1], al[1][2], al[1][3], a_lo1 + co);
            ldsm4(x0, x1, x2, x3, w_hi0 + co);
            bh[0][0] = x0; bh[0][1] = x2; bh[1][0] = x1; bh[1][1] = x3;
            ldsm4(x0, x1, x2, x3, w_hi1 + co);
            bh[2][0] = x0; bh[2][1] = x2; bh[3][0] = x1; bh[3][1] = x3;
            ldsm4(x0, x1, x2, x3, w_lo0 + co);
            bl[0][0] = x0; bl[0][1] = x2; bl[1][0] = x1; bl[1][1] = x3;
            ldsm4(x0, x1, x2, x3, w_lo1 + co);
            bl[2][0] = x0; bl[2][1] = x2; bl[3][0] = x1; bl[3][1] = x3;
#pragma unroll
            for (int i = 0; i < 2; ++i)
#pragma unroll
                for (int j = 0; j < 4; ++j) {
                    mma_bf16(c[i][j], ah[i], bh[j][0], bh[j][1]);
                    mma_bf16(c[i][j], ah[i], bl[j][0], bl[j][1]);
                    mma_bf16(c[i][j], al[i], bh[j][0], bh[j][1]);
                }
        }
        __syncthreads();
    }

    // ---- epilogue: + bias, store fp32 ----
#pragma unroll
    for (int j = 0; j < 4; ++j) {
        const int col = n0g + n0w + j * 8 + 2 * (lane & 3);
        float2 bb = *(const float2*)(bias + col);
#pragma unroll
        for (int i = 0; i < 2; ++i) {
            const int r0 = m0g + m0w + i * 16 + (lane >> 2);
            *(float2*)(out + (size_t)r0 * H_ + col)
                = make_float2(c[i][j][0] + bb.x, c[i][j][1] + bb.y);
            *(float2*)(out + (size_t)(r0 + 8) * H_ + col)
                = make_float2(c[i][j][2] + bb.x, c[i][j][3] + bb.y);
        }
    }
}

// ===================== Phase 2: HMMA recurrence, cone-sync ==================
// ROUND-10 VERSION VERBATIM (proven 6378us path): 128 CTAs = 8 kg x 16 ng,
// CTA M=64 x N=64 x K=128 split-bf16 HMMA, counter-based cone sync,
// single-pass mainloop, both A images staged before compute.
#define A_HI 0
#define A_LO 16384
#define W_HI 32768
#define W_LO 49152
#define RNN_SMEM_BYTES 65536

__global__ void __launch_bounds__(256, 1)
rnn_mma_kernel(const float* __restrict__ W, float* __restrict__ out) {
    extern __shared__ char smem[];
    const uint32_t sb = smem_u32(smem);
    const int tid  = threadIdx.x;
    const int wid  = tid >> 5;
    const int lane = tid & 31;
    const int kg   = blockIdx.x >> 4;    // 0..7
    const int ng   = blockIdx.x & 15;    // 0..15
    const int ksl  = kg * 128;
    const int nsl  = ng * 64;

    // ---- build W^T hi/lo tiles once ----
    for (int q = tid; q < 64 * 128; q += 256) {
        int k = q >> 6;
        int n = q & 63;
        float w = W[(size_t)(ksl + k) * H_ + nsl + n];
        __nv_bfloat16 hi = __float2bfloat16_rn(w);
        __nv_bfloat16 lo = __float2bfloat16_rn(w - __bfloat162float(hi));
        uint32_t off = tswz(n, k);
        *(unsigned short*)(smem + W_HI + off) = *(unsigned short*)&hi;
        *(unsigned short*)(smem + W_LO + off) = *(unsigned short*)&lo;
    }
    __syncthreads();

    const int m0  = (wid & 3) * 16;
    const int n0w = (wid >> 2) * 32;
    const int lr  = lane & 15;
    const int kh  = lane >> 4;

    const uint32_t a_row_hi = sb + A_HI + (uint32_t)((m0 + lr) * 256);
    const uint32_t a_row_lo = sb + A_LO + (uint32_t)((m0 + lr) * 256);
    const uint32_t w_row0_h = sb + W_HI + (uint32_t)((n0w + lr) * 256);
    const uint32_t w_row1_h = sb + W_HI + (uint32_t)((n0w + 16 + lr) * 256);
    const uint32_t w_row0_l = sb + W_LO + (uint32_t)((n0w + lr) * 256);
    const uint32_t w_row1_l = sb + W_LO + (uint32_t)((n0w + 16 + lr) * 256);
    const uint32_t swz_a = (uint32_t)(lane & 7);

    const int ra_ = m0 + (lane >> 2);
    const int rb_ = ra_ + 8;
    const int colb = n0w + 2 * (lane & 3);

    const int e    = tid * 2;
    const int rr   = e >> 6;
    const int cc   = e & 63;
    const int eb   = kg * 8 + rr;
    const int kg2  = ng >> 1;
    const int kimg = (ng & 1) * 64 + cc;
    const uint32_t hoff = tswz(eb, kimg);

    for (int t = 0; t < T_; ++t) {
        // ---- top waits: 4 distinct counters polled by 4 parallel threads ----
        if (tid == 0) {
            poll_ge(&g_prod[2 * kg], 8u * (unsigned)t);          // h cols lo half
        } else if (tid == 32) {
            poll_ge(&g_prod[2 * kg + 1], 8u * (unsigned)t);      // h cols hi half
        } else if (tid == 64) {
            if (t >= 2) poll_ge(&g_prod[ng], 8u * (unsigned)(t - 1)); // g_part WAR
        } else if (tid == 96) {
            if (t >= 1) poll_ge(&g_rdone[kg2], 16u * (unsigned)t);    // h-image WAR
        }
        __syncthreads();

        // ---- prefetch xp (independent) ----
        size_t obase = ((size_t)eb * T_ + t) * H_ + nsl + cc;
        float2 xv = __ldcg((const float2*)(out + obase));

        // ---- stage A hi/lo images (raw 16KB copies; already swizzled) ----
        const uint4* srcH = (const uint4*)(g_hsp[t & 1][0][kg]);
        const uint4* srcL = (const uint4*)(g_hsp[t & 1][1][kg]);
#pragma unroll
        for (int i = 0; i < 4; ++i) {
            uint4 vh = __ldcg(srcH + i * 256 + tid);
            uint4 vl = __ldcg(srcL + i * 256 + tid);
            *(uint4*)(smem + A_HI + i * 4096 + tid * 16) = vh;
            *(uint4*)(smem + A_LO + i * 4096 + tid * 16) = vl;
        }
        __syncthreads();
        if (tid == 0) rel_add1(&g_rdone[kg]);   // h buf read complete

        // ---- mma mainloop: K=128, 8 k16-steps, 3 split products ----
        float c[4][4];
#pragma unroll
        for (int j = 0; j < 4; ++j)
            c[j][0] = c[j][1] = c[j][2] = c[j][3] = 0.f;

#pragma unroll
        for (int s = 0; s < 8; ++s) {
            const uint32_t ca  = (uint32_t)(((2 * s + kh) ^ swz_a) << 4);
            const uint32_t cw0 = (uint32_t)(((2 * s + kh) ^ (lr & 7)) << 4);
            uint32_t ah[4], al[4];
            uint32_t x0, x1, x2, x3;
            ldsm4(ah[0], ah[1], ah[2], ah[3], a_row_hi + ca);
            ldsm4(al[0], al[1], al[2], al[3], a_row_lo + ca);
            ldsm4(x0, x1, x2, x3, w_row0_h + cw0);
            uint32_t bh0 = x0, bh1 = x2, bh0b = x1, bh1b = x3;
            ldsm4(x0, x1, x2, x3, w_row1_h + cw0);
            uint32_t bh2 = x0, bh3 = x2, bh2b = x1, bh3b = x3;
            ldsm4(x0, x1, x2, x3, w_row0_l + cw0);
            uint32_t bl0 = x0, bl1 = x2, bl0b = x1, bl1b = x3;
            ldsm4(x0, x1, x2, x3, w_row1_l + cw0);
            uint32_t bl2 = x0, bl3 = x2, bl2b = x1, bl3b = x3;

            mma_bf16(c[0], ah, bh0, bh1);
            mma_bf16(c[1], ah, bh0b, bh1b);
            mma_bf16(c[2], ah, bh2, bh3);
            mma_bf16(c[3], ah, bh2b, bh3b);
            mma_bf16(c[0], ah, bl0, bl1);
            mma_bf16(c[1], ah, bl0b, bl1b);
            mma_bf16(c[2], ah, bl2, bl3);
            mma_bf16(c[3], ah, bl2b, bl3b);
            mma_bf16(c[0], al, bh0, bh1);
            mma_bf16(c[1], al, bh0b, bh1b);
            mma_bf16(c[2], al, bh2, bh3);
            mma_bf16(c[3], al, bh2b, bh3b);
        }

        // ---- store partials to global (WAR cleared by tid64's top wait) ----
        {
            const int pr = t & 1;
            float* pa = &g_part[pr][kg][(size_t)ra_ * H_ + nsl + colb];
            float* pb = &g_part[pr][kg][(size_t)rb_ * H_ + nsl + colb];
#pragma unroll
            for (int j = 0; j < 4; ++j) {
                __stcg((float2*)(pa + j * 8), make_float2(c[j][0], c[j][1]));
                __stcg((float2*)(pb + j * 8), make_float2(c[j][2], c[j][3]));
            }
        }
        __syncthreads();
        if (tid == 0) {
            rel_add1(&g_bar2[ng]);
            poll_ge(&g_bar2[ng], 8u * (unsigned)(t + 1));  // all 8 kg partials in
        }
        __syncthreads();

        // ---- reduce 8 partials, add xp, tanh, write out + split-h image ----
        {
            const int pr = t & 1;
            float2 s2 = make_float2(0.f, 0.f);
#pragma unroll
            for (int k2 = 0; k2 < 8; ++k2) {
                float2 pv = __ldcg((const float2*)(&g_part[pr][k2][(size_t)eb * H_ + nsl + cc]));
                s2.x += pv.x; s2.y += pv.y;
            }
            float2 hn;
            hn.x = tanhf(s2.x + xv.x);
            hn.y = tanhf(s2.y + xv.y);
            __stcg((float2*)(out + obase), hn);

            uint32_t hp, lp;
            split2(hn.x, hn.y, hp, lp);
            const int nb = (t + 1) & 1;
            __stcg((unsigned int*)(g_hsp[nb][0][kg2] + hoff), hp);
            __stcg((unsigned int*)(g_hsp[nb][1][kg2] + hoff), lp);
        }
        __syncthreads();
        if (tid == 0) rel_add1(&g_prod[ng]);   // h for step t published
    }
}

// ===================== launch ===============================================
extern "C" void kernel_launch(void* const* d_in, const int* in_sizes, int n_in,
                              void* d_out, int out_size) {
    const float *x = nullptr, *hw = nullptr, *iw = nullptr, *bias = nullptr;
    for (int i = 0; i < n_in; ++i) {
        long long s = in_sizes[i];
        if      (s == (long long)B_ * T_ * I_) x    = (const float*)d_in[i];
        else if (s == (long long)H_ * H_)      hw   = (const float*)d_in[i];
        else if (s == (long long)I_ * H_)      iw   = (const float*)d_in[i];
        else if (s == (long long)H_)           bias = (const float*)d_in[i];
    }
    float* out = (float*)d_out;

    cudaFuncSetAttribute(rnn_mma_kernel,
                         cudaFuncAttributeMaxDynamicSharedMemorySize,
                         RNN_SMEM_BYTES);

    convert_iw<<<64, 256>>>(iw);
    proj_mma<<<dim3(8, 1024), 256>>>(x, bias, out);
    init_kernel<<<64, 256>>>();
    rnn_mma_kernel<<<128, 256, RNN_SMEM_BYTES>>>(hw, out);
}

// round 16
// speedup vs baseline: 2.2357x; 1.3200x over previous
#include <cuda_runtime.h>
#include <cuda_bf16.h>
#include <cstdint>
#include <math.h>

#define B_  64
#define T_  1024
#define I_  512
#define H_  1024

// ===================== warp-mma helpers =====================================
__device__ __forceinline__ uint32_t smem_u32(const void* p) {
    uint32_t a;
    asm("{ .reg .u64 t; cvta.to.shared.u64 t, %1; cvt.u32.u64 %0, t; }"
        : "=r"(a) : "l"(p));
    return a;
}
__device__ __forceinline__ void ldsm4(uint32_t& r0, uint32_t& r1,
                                      uint32_t& r2, uint32_t& r3, uint32_t a) {
    asm volatile("ldmatrix.sync.aligned.m8n8.x4.shared.b16 {%0,%1,%2,%3}, [%4];"
                 : "=r"(r0), "=r"(r1), "=r"(r2), "=r"(r3) : "r"(a));
}
__device__ __forceinline__ void mma_bf16(float* c, const uint32_t* a,
                                         uint32_t b0, uint32_t b1) {
    asm volatile("mma.sync.aligned.m16n8k16.row.col.f32.bf16.bf16.f32 "
                 "{%0,%1,%2,%3}, {%4,%5,%6,%7}, {%8,%9}, {%0,%1,%2,%3};"
                 : "+f"(c[0]), "+f"(c[1]), "+f"(c[2]), "+f"(c[3])
                 : "r"(a[0]), "r"(a[1]), "r"(a[2]), "r"(a[3]),
                   "r"(b0), "r"(b1));
}
__device__ __forceinline__ void poll_ge(unsigned* p, unsigned tgt) {
    unsigned v;
    do { asm volatile("ld.acquire.gpu.global.u32 %0, [%1];"
                      : "=r"(v) : "l"(p)); } while (v < tgt);
}
__device__ __forceinline__ void rel_add1(unsigned* p) {
    asm volatile("red.release.gpu.global.add.u32 [%0], 1;" :: "l"(p) : "memory");
}
// split fp32 pair -> packed bf16x2 hi + lo
__device__ __forceinline__ void split2(float a, float b,
                                       uint32_t& h, uint32_t& l) {
    __nv_bfloat16 ha = __float2bfloat16_rn(a);
    __nv_bfloat16 hb = __float2bfloat16_rn(b);
    __nv_bfloat16 la = __float2bfloat16_rn(a - __bfloat162float(ha));
    __nv_bfloat16 lb = __float2bfloat16_rn(b - __bfloat162float(hb));
    __nv_bfloat162 hp; hp.x = ha; hp.y = hb;
    __nv_bfloat162 lp; lp.x = la; lp.y = lb;
    h = *(uint32_t*)&hp; l = *(uint32_t*)&lp;
}
// swizzled offset in a [.][64 k] bf16 tile (128 B rows)
__device__ __forceinline__ uint32_t tswz64c(int row, int chunk) {
    return (uint32_t)(row * 128) + (uint32_t)((chunk ^ (row & 7)) << 4);
}
// swizzled offset in a [.][1024 k] bf16 tile (2048 B rows)
__device__ __forceinline__ uint32_t tswz1k(int row, int k) {
    uint32_t kb = (uint32_t)(k * 2);
    return (uint32_t)(row * 2048) + ((((kb >> 4) ^ (row & 7)) << 4) | (kb & 15));
}

// ===================== global scratch =======================================
// h state as pre-swizzled bf16 tile images: [buf][hi/lo][mg][16 rows x 1024 k]
__device__ unsigned char g_hsp[2][2][4][32768];
__device__ unsigned g_prod[4];                       // per-mg step counters
__device__ __nv_bfloat16 g_iwt[2][H_ * I_];          // input_w^T hi/lo [n][k]

__global__ void init_kernel() {
    int idx = blockIdx.x * blockDim.x + threadIdx.x;   // 16384 threads
    ((uint4*)g_hsp[0])[idx] = make_uint4(0, 0, 0, 0);  // zero buf 0 (h0 = 0)
    if (idx < 4) g_prod[idx] = 0u;
}

// ===================== Phase 0: transpose + split input_w ===================
__global__ void __launch_bounds__(256)
convert_iw(const float* __restrict__ iw) {
    const int tid  = threadIdx.x;
    const int lane = tid & 31;
    const int gw   = blockIdx.x * 8 + (tid >> 5);   // 0..511
    const int n0   = (gw & 31) * 32;
    const int k0   = (gw >> 5) * 32;
    const int n    = n0 + lane;

    float w[32];
#pragma unroll
    for (int kr = 0; kr < 32; ++kr)
        w[kr] = iw[(size_t)(k0 + kr) * H_ + n];

    uint32_t hu[16], lu[16];
#pragma unroll
    for (int j = 0; j < 16; ++j)
        split2(w[2 * j], w[2 * j + 1], hu[j], lu[j]);

    char* dh = (char*)g_iwt[0] + (size_t)n * 1024 + k0 * 2;
    char* dl = (char*)g_iwt[1] + (size_t)n * 1024 + k0 * 2;
#pragma unroll
    for (int j = 0; j < 4; ++j) {
        *(uint4*)(dh + j * 16) = *(uint4*)&hu[j * 4];
        *(uint4*)(dl + j * 16) = *(uint4*)&lu[j * 4];
    }
}

// ===================== Phase 1: xp = x @ input_w + b (HMMA) =================
#define PJ_A_HI 0
#define PJ_A_LO 8192
#define PJ_W_HI 16384
#define PJ_W_LO 32768

__global__ void __launch_bounds__(256, 2)
proj_mma(const float* __restrict__ x, const float* __restrict__ bias,
         float* __restrict__ out) {
    __shared__ char smem[49152];
    const uint32_t sb = smem_u32(smem);
    const int tid  = threadIdx.x;
    const int wid  = tid >> 5;
    const int lane = tid & 31;
    const int n0g  = blockIdx.x * 128;
    const int m0g  = blockIdx.y * 64;

    const int m0w = (wid & 1) * 32;
    const int n0w = (wid >> 1) * 32;
    const int lr  = lane & 15;
    const int kh  = lane >> 4;

    const uint32_t a_hi0 = sb + PJ_A_HI + (uint32_t)((m0w + lr) * 128);
    const uint32_t a_hi1 = a_hi0 + 16 * 128;
    const uint32_t a_lo0 = sb + PJ_A_LO + (uint32_t)((m0w + lr) * 128);
    const uint32_t a_lo1 = a_lo0 + 16 * 128;
    const uint32_t w_hi0 = sb + PJ_W_HI + (uint32_t)((n0w + lr) * 128);
    const uint32_t w_hi1 = w_hi0 + 16 * 128;
    const uint32_t w_lo0 = sb + PJ_W_LO + (uint32_t)((n0w + lr) * 128);
    const uint32_t w_lo1 = w_lo0 + 16 * 128;

    float c[2][4][4];
#pragma unroll
    for (int i = 0; i < 2; ++i)
#pragma unroll
        for (int j = 0; j < 4; ++j)
            c[i][j][0] = c[i][j][1] = c[i][j][2] = c[i][j][3] = 0.f;

    const int arow = tid >> 2, akq = tid & 3;
    const int wrow = tid >> 1, whalf = tid & 1;

    for (int kt = 0; kt < 8; ++kt) {
        {
            const float* src = x + (size_t)(m0g + arow) * I_ + kt * 64 + akq * 16;
            float4 f0 = *(const float4*)(src + 0);
            float4 f1 = *(const float4*)(src + 4);
            float4 f2 = *(const float4*)(src + 8);
            float4 f3 = *(const float4*)(src + 12);
            uint32_t hu[8], lu[8];
            split2(f0.x, f0.y, hu[0], lu[0]); split2(f0.z, f0.w, hu[1], lu[1]);
            split2(f1.x, f1.y, hu[2], lu[2]); split2(f1.z, f1.w, hu[3], lu[3]);
            split2(f2.x, f2.y, hu[4], lu[4]); split2(f2.z, f2.w, hu[5], lu[5]);
            split2(f3.x, f3.y, hu[6], lu[6]); split2(f3.z, f3.w, hu[7], lu[7]);
#pragma unroll
            for (int c8 = 0; c8 < 2; ++c8) {
                uint32_t off = tswz64c(arow, akq * 2 + c8);
                *(uint4*)(smem + PJ_A_HI + off) = *(uint4*)&hu[c8 * 4];
                *(uint4*)(smem + PJ_A_LO + off) = *(uint4*)&lu[c8 * 4];
            }
        }
        {
            const char* sh = (const char*)g_iwt[0]
                           + (size_t)(n0g + wrow) * 1024 + kt * 128 + whalf * 64;
            const char* sl = (const char*)g_iwt[1]
                           + (size_t)(n0g + wrow) * 1024 + kt * 128 + whalf * 64;
#pragma unroll
            for (int j = 0; j < 4; ++j) {
                uint4 vh = __ldcg((const uint4*)(sh + j * 16));
                uint4 vl = __ldcg((const uint4*)(sl + j * 16));
                uint32_t off = tswz64c(wrow, whalf * 4 + j);
                *(uint4*)(smem + PJ_W_HI + off) = vh;
                *(uint4*)(smem + PJ_W_LO + off) = vl;
            }
        }
        __syncthreads();

#pragma unroll
        for (int s = 0; s < 4; ++s) {
            const uint32_t co = (uint32_t)(((2 * s + kh) ^ (lr & 7)) << 4);
            uint32_t ah[2][4], al[2][4], bh[4][2], bl[4][2];
            uint32_t x0, x1, x2, x3;
            ldsm4(ah[0][0], ah[0][1], ah[0][2], ah[0][3], a_hi0 + co);
            ldsm4(ah[1][0], ah[1][1], ah[1][2], ah[1][3], a_hi1 + co);
            ldsm4(al[0][0], al[0][1], al[0][2], al[0][3], a_lo0 + co);
            ldsm4(al[1][0], al[1][1], al[1][2], al[1][3], a_lo1 + co);
            ldsm4(x0, x1, x2, x3, w_hi0 + co);
            bh[0][0] = x0; bh[0][1] = x2; bh[1][0] = x1; bh[1][1] = x3;
            ldsm4(x0, x1, x2, x3, w_hi1 + co);
            bh[2][0] = x0; bh[2][1] = x2; bh[3][0] = x1; bh[3][1] = x3;
            ldsm4(x0, x1, x2, x3, w_lo0 + co);
            bl[0][0] = x0; bl[0][1] = x2; bl[1][0] = x1; bl[1][1] = x3;
            ldsm4(x0, x1, x2, x3, w_lo1 + co);
            bl[2][0] = x0; bl[2][1] = x2; bl[3][0] = x1; bl[3][1] = x3;
#pragma unroll
            for (int i = 0; i < 2; ++i)
#pragma unroll
                for (int j = 0; j < 4; ++j) {
                    mma_bf16(c[i][j], ah[i], bh[j][0], bh[j][1]);
                    mma_bf16(c[i][j], ah[i], bl[j][0], bl[j][1]);
                    mma_bf16(c[i][j], al[i], bh[j][0], bh[j][1]);
                }
        }
        __syncthreads();
    }

#pragma unroll
    for (int j = 0; j < 4; ++j) {
        const int col = n0g + n0w + j * 8 + 2 * (lane & 3);
        float2 bb = *(const float2*)(bias + col);
#pragma unroll
        for (int i = 0; i < 2; ++i) {
            const int r0 = m0g + m0w + i * 16 + (lane >> 2);
            *(float2*)(out + (size_t)r0 * H_ + col)
                = make_float2(c[i][j][0] + bb.x, c[i][j][1] + bb.y);
            *(float2*)(out + (size_t)(r0 + 8) * H_ + col)
                = make_float2(c[i][j][2] + bb.x, c[i][j][3] + bb.y);
        }
    }
}

// ===================== Phase 2: HMMA recurrence, full-K CTAs ================
// 128 CTAs = 4 m-groups x 32 n-groups. CTA: M=16 x N=32 x K=1024 split-bf16.
// K split 8 ways ACROSS WARPS (intra-CTA SMEM reduce — no global partials).
// ONE counter wait + ONE arrival per step (covers RAW and WAR transitively).
#define A_HI   0                    // 16 x 1024 bf16 = 32 KB
#define A_LO   32768
#define W_HI   65536                // 32 x 1024 bf16 = 64 KB
#define W_LO   131072
#define RED    196608               // 8 x 16 x 34 fp32 = 17408 B
#define RSTR   34
#define RNN_SMEM_BYTES (196608 + 8 * 16 * RSTR * 4)

__global__ void __launch_bounds__(256, 1)
rnn_mma_kernel(const float* __restrict__ W, float* __restrict__ out) {
    extern __shared__ char smem[];
    const uint32_t sb = smem_u32(smem);
    float* red = (float*)(smem + RED);
    const int tid  = threadIdx.x;
    const int wid  = tid >> 5;
    const int lane = tid & 31;
    const int mg   = blockIdx.x >> 5;    // 0..3
    const int ng   = blockIdx.x & 31;    // 0..31
    const int nsl  = ng * 32;

    // ---- build W^T hi/lo tiles once: Wt[n][k] = W[k][nsl+n], swizzled ----
    for (int q = tid; q < 32 * 1024; q += 256) {
        int n = q & 31;                  // coalesced along n
        int k = q >> 5;
        float w = W[(size_t)k * H_ + nsl + n];
        __nv_bfloat16 hi = __float2bfloat16_rn(w);
        __nv_bfloat16 lo = __float2bfloat16_rn(w - __bfloat162float(hi));
        uint32_t off = tswz1k(n, k);
        *(unsigned short*)(smem + W_HI + off) = *(unsigned short*)&hi;
        *(unsigned short*)(smem + W_LO + off) = *(unsigned short*)&lo;
    }
    __syncthreads();

    const int lr = lane & 15;
    const int kh = lane >> 4;

    // per-warp K slice = chunks [wid*16, wid*16+16)  (16B chunks of 8 bf16)
    const uint32_t a_hi = sb + A_HI + (uint32_t)(lr * 2048);
    const uint32_t a_lo = sb + A_LO + (uint32_t)(lr * 2048);
    const uint32_t w_h0 = sb + W_HI + (uint32_t)(lr * 2048);
    const uint32_t w_h1 = sb + W_HI + (uint32_t)((16 + lr) * 2048);
    const uint32_t w_l0 = sb + W_LO + (uint32_t)(lr * 2048);
    const uint32_t w_l1 = sb + W_LO + (uint32_t)((16 + lr) * 2048);
    const uint32_t swz = (uint32_t)(lane & 7);

    // epilogue assignment: 2 output elems (float2) per thread
    const int e   = tid * 2;
    const int rr  = e >> 5;              // 0..15 local row
    const int cc  = e & 31;              // even col in n-slice
    const int gr  = mg * 16 + rr;        // global batch row
    const uint32_t hoff = tswz1k(rr, nsl + cc);

    for (int t = 0; t < T_; ++t) {
        // ---- single wait: all 32 CTAs of this mg finished step t-1 ----
        if (tid == 0) poll_ge(&g_prod[mg], 32u * (unsigned)t);
        __syncthreads();

        // ---- prefetch xp (independent) ----
        size_t obase = ((size_t)gr * T_ + t) * H_ + nsl + cc;
        float2 xv = __ldcg((const float2*)(out + obase));

        // ---- stage A hi/lo images (raw 32KB copies; already swizzled) ----
        const uint4* srcH = (const uint4*)(g_hsp[t & 1][0][mg]);
        const uint4* srcL = (const uint4*)(g_hsp[t & 1][1][mg]);
#pragma unroll
        for (int i = 0; i < 8; ++i) {
            uint4 vh = __ldcg(srcH + i * 256 + tid);
            uint4 vl = __ldcg(srcL + i * 256 + tid);
            *(uint4*)(smem + A_HI + i * 4096 + tid * 16) = vh;
            *(uint4*)(smem + A_LO + i * 4096 + tid * 16) = vl;
        }
        __syncthreads();

        // ---- mma: warp's 128-k slice, 8 k16-steps, 3 split products ----
        float c[4][4];
#pragma unroll
        for (int j = 0; j < 4; ++j)
            c[j][0] = c[j][1] = c[j][2] = c[j][3] = 0.f;

#pragma unroll
        for (int s = 0; s < 8; ++s) {
            const uint32_t ch  = (uint32_t)(wid * 16 + 2 * s + kh);
            const uint32_t ca  = ((ch ^ swz) << 4);
            const uint32_t cw  = ((ch ^ (uint32_t)(lr & 7)) << 4);
            uint32_t ah[4], al[4];
            uint32_t x0, x1, x2, x3;
            ldsm4(ah[0], ah[1], ah[2], ah[3], a_hi + ca);
            ldsm4(al[0], al[1], al[2], al[3], a_lo + ca);
            ldsm4(x0, x1, x2, x3, w_h0 + cw);
            uint32_t bh0 = x0, bh1 = x2, bh0b = x1, bh1b = x3;
            ldsm4(x0, x1, x2, x3, w_h1 + cw);
            uint32_t bh2 = x0, bh3 = x2, bh2b = x1, bh3b = x3;
            ldsm4(x0, x1, x2, x3, w_l0 + cw);
            uint32_t bl0 = x0, bl1 = x2, bl0b = x1, bl1b = x3;
            ldsm4(x0, x1, x2, x3, w_l1 + cw);
            uint32_t bl2 = x0, bl3 = x2, bl2b = x1, bl3b = x3;

            mma_bf16(c[0], ah, bh0, bh1);
            mma_bf16(c[1], ah, bh0b, bh1b);
            mma_bf16(c[2], ah, bh2, bh3);
            mma_bf16(c[3], ah, bh2b, bh3b);
            mma_bf16(c[0], ah, bl0, bl1);
            mma_bf16(c[1], ah, bl0b, bl1b);
            mma_bf16(c[2], ah, bl2, bl3);
            mma_bf16(c[3], ah, bl2b, bl3b);
            mma_bf16(c[0], al, bh0, bh1);
            mma_bf16(c[1], al, bh0b, bh1b);
            mma_bf16(c[2], al, bh2, bh3);
            mma_bf16(c[3], al, bh2b, bh3b);
        }

        // ---- intra-CTA K-reduction via SMEM ----
        __syncthreads();                 // A reads done (red aliases nothing)
        {
            const int r0 = lane >> 2;
            const int cb = 2 * (lane & 3);
#pragma unroll
            for (int j = 0; j < 4; ++j) {
                *(float2*)&red[(wid * 16 + r0) * RSTR + j * 8 + cb]
                    = make_float2(c[j][0], c[j][1]);
                *(float2*)&red[(wid * 16 + r0 + 8) * RSTR + j * 8 + cb]
                    = make_float2(c[j][2], c[j][3]);
            }
        }
        __syncthreads();

        // ---- reduce 8 warps, add xp, tanh, write out + split-h image ----
        {
            float2 s2 = make_float2(0.f, 0.f);
#pragma unroll
            for (int w8 = 0; w8 < 8; ++w8) {
                float2 pv = *(const float2*)&red[(w8 * 16 + rr) * RSTR + cc];
                s2.x += pv.x; s2.y += pv.y;
            }
            float2 hn;
            hn.x = tanhf(s2.x + xv.x);
            hn.y = tanhf(s2.y + xv.y);
            __stcg((float2*)(out + obase), hn);

            uint32_t hp, lp;
            split2(hn.x, hn.y, hp, lp);
            const int nb = (t + 1) & 1;
            __stcg((unsigned int*)(g_hsp[nb][0][mg] + hoff), hp);
            __stcg((unsigned int*)(g_hsp[nb][1][mg] + hoff), lp);
        }
        __syncthreads();
        if (tid == 0) rel_add1(&g_prod[mg]);   // step t fully done
    }
}

// ===================== launch ===============================================
extern "C" void kernel_launch(void* const* d_in, const int* in_sizes, int n_in,
                              void* d_out, int out_size) {
    const float *x = nullptr, *hw = nullptr, *iw = nullptr, *bias = nullptr;
    for (int i = 0; i < n_in; ++i) {
        long long s = in_sizes[i];
        if      (s == (long long)B_ * T_ * I_) x    = (const float*)d_in[i];
        else if (s == (long long)H_ * H_)      hw   = (const float*)d_in[i];
        else if (s == (long long)I_ * H_)      iw   = (const float*)d_in[i];
        else if (s == (long long)H_)           bias = (const float*)d_in[i];
    }
    float* out = (float*)d_out;

    cudaFuncSetAttribute(rnn_mma_kernel,
                         cudaFuncAttributeMaxDynamicSharedMemorySize,
                         RNN_SMEM_BYTES);

    convert_iw<<<64, 256>>>(iw);
    proj_mma<<<dim3(8, 1024), 256>>>(x, bias, out);
    init_kernel<<<64, 256>>>();
    rnn_mma_kernel<<<128, 256, RNN_SMEM_BYTES>>>(hw, out);
}